// round 2
// baseline (speedup 1.0000x reference)
#include <cuda_runtime.h>
#include <math_constants.h>

#define B_SZ 2
#define L_SEQ 2048
#define D_MODEL 1024
#define NH 16
#define DK 64
#define M_TOT (B_SZ * L_SEQ)
#define ST 68  // smem row stride (floats) for 64-wide tiles in attention

// Scratch (device globals — no cudaMalloc allowed)
__device__ float g_Qh[B_SZ * NH * L_SEQ * DK];   // [b][h][i][d]
__device__ float g_Kh[B_SZ * NH * L_SEQ * DK];
__device__ float g_Vh[B_SZ * NH * L_SEQ * DK];
__device__ float g_Mha[M_TOT * D_MODEL];         // [b*L+i][d*16+h]
__device__ unsigned char g_mask[B_SZ * L_SEQ * L_SEQ];  // packed byte mask

// ---------------------------------------------------------------------------
// Mask conversion: input arrives as 4-byte elements (int32 or float32 from a
// bool array). Nonzero bits == masked. Pack to 1 byte/elem.
// ---------------------------------------------------------------------------
__global__ __launch_bounds__(256) void mask_cvt_kernel(
    const int* __restrict__ m4, unsigned char* __restrict__ out) {
  int i = blockIdx.x * 256 + threadIdx.x;  // one thread = 4 elements
  const int4 v = ((const int4*)m4)[i];
  uchar4 o;
  o.x = v.x != 0;
  o.y = v.y != 0;
  o.z = v.z != 0;
  o.w = v.w != 0;
  ((uchar4*)out)[i] = o;
}

// ---------------------------------------------------------------------------
// GEMM: C[m,n] = sum_k A[m,k] * W[n,k]   (A: M x K row-major, W: N x K row-major)
// M=4096, N=1024, K=1024.
// MODE 0: store C[m*1024 + n] (standard)
// MODE 1: store head-scattered: h = n%16, d = n/16, b = m/2048, i = m%2048
//         -> C[(((b*16+h)*2048)+i)*64 + d]
// ---------------------------------------------------------------------------
template <int MODE>
__global__ __launch_bounds__(256) void gemm_nt_kernel(
    const float* __restrict__ A, const float* __restrict__ W,
    float* __restrict__ C) {
  const int K = D_MODEL;
  __shared__ float As[16][132];
  __shared__ float Ws[16][132];
  int tid = threadIdx.x;
  int m0 = blockIdx.y * 128;
  int n0 = blockIdx.x * 128;
  int lr = tid >> 2;          // 0..63
  int lc = (tid & 3) << 2;    // 0,4,8,12
  int ty = tid >> 4;          // 0..15
  int tx = tid & 15;          // 0..15

  float acc[8][8];
#pragma unroll
  for (int i = 0; i < 8; i++)
#pragma unroll
    for (int j = 0; j < 8; j++) acc[i][j] = 0.f;

  for (int k0 = 0; k0 < K; k0 += 16) {
#pragma unroll
    for (int s = 0; s < 2; s++) {
      int row = lr + s * 64;
      float4 a = *(const float4*)&A[(size_t)(m0 + row) * K + k0 + lc];
      As[lc + 0][row] = a.x;
      As[lc + 1][row] = a.y;
      As[lc + 2][row] = a.z;
      As[lc + 3][row] = a.w;
      float4 w = *(const float4*)&W[(size_t)(n0 + row) * K + k0 + lc];
      Ws[lc + 0][row] = w.x;
      Ws[lc + 1][row] = w.y;
      Ws[lc + 2][row] = w.z;
      Ws[lc + 3][row] = w.w;
    }
    __syncthreads();
#pragma unroll
    for (int kk = 0; kk < 16; kk++) {
      float a[8], b[8];
      *(float4*)&a[0] = *(const float4*)&As[kk][ty * 8];
      *(float4*)&a[4] = *(const float4*)&As[kk][ty * 8 + 4];
      *(float4*)&b[0] = *(const float4*)&Ws[kk][tx * 8];
      *(float4*)&b[4] = *(const float4*)&Ws[kk][tx * 8 + 4];
#pragma unroll
      for (int i = 0; i < 8; i++)
#pragma unroll
        for (int j = 0; j < 8; j++) acc[i][j] += a[i] * b[j];
    }
    __syncthreads();
  }

  if (MODE == 0) {
#pragma unroll
    for (int i = 0; i < 8; i++) {
      int m = m0 + ty * 8 + i;
      float* dst = &C[(size_t)m * D_MODEL + n0 + tx * 8];
      *(float4*)&dst[0] = make_float4(acc[i][0], acc[i][1], acc[i][2], acc[i][3]);
      *(float4*)&dst[4] = make_float4(acc[i][4], acc[i][5], acc[i][6], acc[i][7]);
    }
  } else {
#pragma unroll
    for (int i = 0; i < 8; i++) {
      int m = m0 + ty * 8 + i;
      int b = m >> 11;             // /2048
      int ii = m & (L_SEQ - 1);
#pragma unroll
      for (int j = 0; j < 8; j++) {
        int n = n0 + tx * 8 + j;
        int h = n & 15;
        int d = n >> 4;
        C[((((size_t)b * NH + h) * L_SEQ) + ii) * DK + d] = acc[i][j];
      }
    }
  }
}

// ---------------------------------------------------------------------------
// Attention: one block per (b, h, 64-row i-tile). Online softmax over 64-wide
// o-tiles. Q/K stored d-major in smem, V o-major, P i-major.
// ---------------------------------------------------------------------------
__global__ __launch_bounds__(256) void attn_kernel(
    const float* __restrict__ Qh, const float* __restrict__ Kh,
    const float* __restrict__ Vh, const unsigned char* __restrict__ mask,
    float* __restrict__ Mha) {
  extern __shared__ float sm[];
  float* Qs = sm;                        // [64][ST]  Qs[d][i] (scaled)
  float* Ks = sm + 64 * ST;              // [64][ST]  Ks[d][o]
  float* Vs = sm + 2 * 64 * ST;          // [64][ST]  Vs[o][d]
  float* Ps = sm + 3 * 64 * ST;          // [64][ST]  Ps[i][o]
  float* Cs = sm + 4 * 64 * ST;          // [64] per-row rescale factor
  float* Ls = Cs + 64;                   // [64] per-row denom
  unsigned char* Msm = (unsigned char*)(Cs + 128);  // [64][64] mask bytes

  int tid = threadIdx.x;
  int it0 = blockIdx.x * 64;
  int h = blockIdx.y;
  int b = blockIdx.z;
  int bh = b * NH + h;
  const float* Qbase = Qh + (size_t)bh * L_SEQ * DK;
  const float* Kbase = Kh + (size_t)bh * L_SEQ * DK;
  const float* Vbase = Vh + (size_t)bh * L_SEQ * DK;
  const unsigned char* Mbase = mask + (size_t)b * L_SEQ * L_SEQ;

  int ti = tid >> 4, tj = tid & 15;   // 4x4 micro-tile owner
  int sr = tid >> 2, sg = tid & 3;    // softmax: row, quarter

  // Load Q tile transposed + pre-scaled by 1/sqrt(dk)=0.125
  for (int idx = tid; idx < 64 * 16; idx += 256) {
    int i = idx >> 4, dc = (idx & 15) << 2;
    float4 qv = *(const float4*)&Qbase[(size_t)(it0 + i) * DK + dc];
    Qs[(dc + 0) * ST + i] = qv.x * 0.125f;
    Qs[(dc + 1) * ST + i] = qv.y * 0.125f;
    Qs[(dc + 2) * ST + i] = qv.z * 0.125f;
    Qs[(dc + 3) * ST + i] = qv.w * 0.125f;
  }

  float m_run = -CUDART_INF_F;
  float l_run = 0.f;
  float acc[4][4];
#pragma unroll
  for (int r = 0; r < 4; r++)
#pragma unroll
    for (int c = 0; c < 4; c++) acc[r][c] = 0.f;

  for (int ot = 0; ot < L_SEQ / 64; ot++) {
    int o0 = ot * 64;
    // load K (transposed), V (direct), mask tile
    for (int idx = tid; idx < 64 * 16; idx += 256) {
      int o = idx >> 4, dc = (idx & 15) << 2;
      float4 kv = *(const float4*)&Kbase[(size_t)(o0 + o) * DK + dc];
      Ks[(dc + 0) * ST + o] = kv.x;
      Ks[(dc + 1) * ST + o] = kv.y;
      Ks[(dc + 2) * ST + o] = kv.z;
      Ks[(dc + 3) * ST + o] = kv.w;
      float4 vv = *(const float4*)&Vbase[(size_t)(o0 + o) * DK + dc];
      *(float4*)&Vs[o * ST + dc] = vv;
    }
    for (int idx = tid; idx < 64 * 4; idx += 256) {
      int r = idx >> 2, c = idx & 3;
      *(int4*)&Msm[r * 64 + c * 16] =
          *(const int4*)&Mbase[(size_t)(it0 + r) * L_SEQ + o0 + c * 16];
    }
    __syncthreads();

    // S = (Q/8) K^T
    float s[4][4];
#pragma unroll
    for (int r = 0; r < 4; r++)
#pragma unroll
      for (int c = 0; c < 4; c++) s[r][c] = 0.f;
#pragma unroll 16
    for (int d = 0; d < 64; d++) {
      float4 q = *(const float4*)&Qs[d * ST + ti * 4];
      float4 k = *(const float4*)&Ks[d * ST + tj * 4];
      float qa[4] = {q.x, q.y, q.z, q.w};
      float kb[4] = {k.x, k.y, k.z, k.w};
#pragma unroll
      for (int r = 0; r < 4; r++)
#pragma unroll
        for (int c = 0; c < 4; c++) s[r][c] += qa[r] * kb[c];
    }
    // mask + write P tile
#pragma unroll
    for (int r = 0; r < 4; r++) {
      uchar4 mk = *(const uchar4*)&Msm[(ti * 4 + r) * 64 + tj * 4];
      if (mk.x) s[r][0] = -1e10f;
      if (mk.y) s[r][1] = -1e10f;
      if (mk.z) s[r][2] = -1e10f;
      if (mk.w) s[r][3] = -1e10f;
      *(float4*)&Ps[(ti * 4 + r) * ST + tj * 4] =
          make_float4(s[r][0], s[r][1], s[r][2], s[r][3]);
    }
    __syncthreads();

    // online softmax: 4 threads per row, 16 cols each
    {
      float* row = Ps + sr * ST + sg * 16;
      float mx = row[0];
#pragma unroll
      for (int j = 1; j < 16; j++) mx = fmaxf(mx, row[j]);
      mx = fmaxf(mx, __shfl_xor_sync(0xffffffffu, mx, 1));
      mx = fmaxf(mx, __shfl_xor_sync(0xffffffffu, mx, 2));
      float newm = fmaxf(m_run, mx);
      float corr = __expf(m_run - newm);
      float ssum = 0.f;
#pragma unroll
      for (int j = 0; j < 16; j++) {
        float p = __expf(row[j] - newm);
        row[j] = p;
        ssum += p;
      }
      ssum += __shfl_xor_sync(0xffffffffu, ssum, 1);
      ssum += __shfl_xor_sync(0xffffffffu, ssum, 2);
      l_run = l_run * corr + ssum;
      m_run = newm;
      if (sg == 0) Cs[sr] = corr;
    }
    __syncthreads();

    // O = O*corr + P @ V
    {
      float cr[4];
#pragma unroll
      for (int r = 0; r < 4; r++) cr[r] = Cs[ti * 4 + r];
#pragma unroll
      for (int r = 0; r < 4; r++)
#pragma unroll
        for (int c = 0; c < 4; c++) acc[r][c] *= cr[r];
#pragma unroll 16
      for (int o = 0; o < 64; o++) {
        float p0 = Ps[(ti * 4 + 0) * ST + o];
        float p1 = Ps[(ti * 4 + 1) * ST + o];
        float p2 = Ps[(ti * 4 + 2) * ST + o];
        float p3 = Ps[(ti * 4 + 3) * ST + o];
        float4 v = *(const float4*)&Vs[o * ST + tj * 4];
        float vb[4] = {v.x, v.y, v.z, v.w};
#pragma unroll
        for (int c = 0; c < 4; c++) {
          acc[0][c] += p0 * vb[c];
          acc[1][c] += p1 * vb[c];
          acc[2][c] += p2 * vb[c];
          acc[3][c] += p3 * vb[c];
        }
      }
    }
    __syncthreads();
  }

  if (sg == 0) Ls[sr] = l_run;
  __syncthreads();

  float inv[4];
#pragma unroll
  for (int r = 0; r < 4; r++) inv[r] = 1.0f / Ls[ti * 4 + r];
#pragma unroll
  for (int r = 0; r < 4; r++) {
    int i = it0 + ti * 4 + r;
#pragma unroll
    for (int c = 0; c < 4; c++) {
      int d = tj * 4 + c;
      Mha[(size_t)(b * L_SEQ + i) * D_MODEL + d * 16 + h] = acc[r][c] * inv[r];
    }
  }
}

// ---------------------------------------------------------------------------
extern "C" void kernel_launch(void* const* d_in, const int* in_sizes, int n_in,
                              void* d_out, int out_size) {
  const float* q = (const float*)d_in[0];
  const float* k = (const float*)d_in[1];
  const float* v = (const float*)d_in[2];
  const int* mask4 = (const int*)d_in[3];
  const float* Wq = (const float*)d_in[4];
  const float* Wk = (const float*)d_in[5];
  const float* Wv = (const float*)d_in[6];
  const float* Wo = (const float*)d_in[7];
  float* out = (float*)d_out;

  float *Qh, *Kh, *Vh, *Mh;
  unsigned char* Mk;
  cudaGetSymbolAddress((void**)&Qh, g_Qh);
  cudaGetSymbolAddress((void**)&Kh, g_Kh);
  cudaGetSymbolAddress((void**)&Vh, g_Vh);
  cudaGetSymbolAddress((void**)&Mh, g_Mha);
  cudaGetSymbolAddress((void**)&Mk, g_mask);

  // Convert 4-byte mask elements (int32 or float32 bool) -> packed bytes
  int nmask = B_SZ * L_SEQ * L_SEQ;            // 8388608 elements
  mask_cvt_kernel<<<nmask / 4 / 256, 256>>>(mask4, Mk);

  dim3 gg(D_MODEL / 128, M_TOT / 128);  // (8, 32)
  gemm_nt_kernel<1><<<gg, 256>>>(q, Wq, Qh);
  gemm_nt_kernel<1><<<gg, 256>>>(k, Wk, Kh);
  gemm_nt_kernel<1><<<gg, 256>>>(v, Wv, Vh);

  int smem_bytes = (4 * 64 * ST + 128) * 4 + 64 * 64;  // 74240
  cudaFuncSetAttribute(attn_kernel,
                       cudaFuncAttributeMaxDynamicSharedMemorySize, smem_bytes);
  dim3 ag(L_SEQ / 64, NH, B_SZ);
  attn_kernel<<<ag, 256, smem_bytes>>>(Qh, Kh, Vh, Mk, Mh);

  gemm_nt_kernel<0><<<gg, 256>>>(Mh, Wo, out);
}

// round 3
// speedup vs baseline: 1.4400x; 1.4400x over previous
#include <cuda_runtime.h>
#include <math_constants.h>

#define B_SZ 2
#define L_SEQ 2048
#define D_MODEL 1024
#define NH 16
#define DK 64
#define M_TOT (B_SZ * L_SEQ)
#define ST 68  // smem row stride (floats) for 64-wide tiles in attention

// Scratch (device globals — no cudaMalloc allowed)
__device__ float g_Qh[B_SZ * NH * L_SEQ * DK];   // [b][h][i][d]
__device__ float g_Kh[B_SZ * NH * L_SEQ * DK];
__device__ float g_Vh[B_SZ * NH * L_SEQ * DK];
__device__ float g_Mha[M_TOT * D_MODEL];         // [b*L+i][d*16+h]
__device__ unsigned char g_mask[B_SZ * L_SEQ * L_SEQ];  // packed byte mask

__device__ __forceinline__ unsigned f2tf32(float v) {
  unsigned r;
  asm("cvt.rna.tf32.f32 %0, %1;" : "=r"(r) : "f"(v));
  return r;
}

// ---------------------------------------------------------------------------
// Mask conversion: 4-byte bool elements -> packed bytes (nonzero == masked)
// ---------------------------------------------------------------------------
__global__ __launch_bounds__(256) void mask_cvt_kernel(
    const int* __restrict__ m4, unsigned char* __restrict__ out) {
  int i = blockIdx.x * 256 + threadIdx.x;  // one thread = 4 elements
  const int4 v = ((const int4*)m4)[i];
  uchar4 o;
  o.x = v.x != 0;
  o.y = v.y != 0;
  o.z = v.z != 0;
  o.w = v.w != 0;
  ((uchar4*)out)[i] = o;
}

// ---------------------------------------------------------------------------
// TF32 tensor-core GEMM: C[m,n] = sum_k A[m,k] * W[n,k]
// A: M x K row-major, W: N x K row-major. M=4096, N=1024, K=1024.
// CTA: 128x128 tile, KC=32. 8 warps, each 64x32 via 4x4 m16n8k8 mma tiles.
// MODE 0: C[m*1024+n].  MODE 1: head-scatter C[(((b*16+h)*2048)+i)*64+d].
// ---------------------------------------------------------------------------
#define ASTR 36
template <int MODE>
__global__ __launch_bounds__(256) void gemm_tf32_kernel(
    const float* __restrict__ A, const float* __restrict__ W,
    float* __restrict__ C) {
  const int K = D_MODEL;
  __shared__ unsigned As[128 * ASTR];
  __shared__ unsigned Bs[128 * ASTR];

  int tid = threadIdx.x;
  int m0 = blockIdx.y * 128;
  int n0 = blockIdx.x * 128;
  int wid = tid >> 5;
  int lane = tid & 31;
  int warp_m = (wid & 1) * 64;   // 0 or 64
  int warp_n = (wid >> 1) * 32;  // 0,32,64,96
  int grp = lane >> 2;           // 0..7
  int thr = lane & 3;            // 0..3

  float acc[4][4][4];
#pragma unroll
  for (int i = 0; i < 4; i++)
#pragma unroll
    for (int j = 0; j < 4; j++)
#pragma unroll
      for (int r = 0; r < 4; r++) acc[i][j][r] = 0.f;

  int lr = tid >> 3;        // 0..31 row group
  int lc = (tid & 7) * 4;   // col*4

  for (int k0 = 0; k0 < K; k0 += 32) {
#pragma unroll
    for (int s = 0; s < 4; s++) {
      int r = lr + s * 32;
      float4 a = *(const float4*)&A[(size_t)(m0 + r) * K + k0 + lc];
      As[r * ASTR + lc + 0] = f2tf32(a.x);
      As[r * ASTR + lc + 1] = f2tf32(a.y);
      As[r * ASTR + lc + 2] = f2tf32(a.z);
      As[r * ASTR + lc + 3] = f2tf32(a.w);
      float4 w = *(const float4*)&W[(size_t)(n0 + r) * K + k0 + lc];
      Bs[r * ASTR + lc + 0] = f2tf32(w.x);
      Bs[r * ASTR + lc + 1] = f2tf32(w.y);
      Bs[r * ASTR + lc + 2] = f2tf32(w.z);
      Bs[r * ASTR + lc + 3] = f2tf32(w.w);
    }
    __syncthreads();

#pragma unroll
    for (int kk = 0; kk < 32; kk += 8) {
      unsigned af[4][4], bf[4][2];
#pragma unroll
      for (int mt = 0; mt < 4; mt++) {
        int rb = warp_m + mt * 16;
        af[mt][0] = As[(rb + grp) * ASTR + kk + thr];
        af[mt][1] = As[(rb + grp + 8) * ASTR + kk + thr];
        af[mt][2] = As[(rb + grp) * ASTR + kk + thr + 4];
        af[mt][3] = As[(rb + grp + 8) * ASTR + kk + thr + 4];
      }
#pragma unroll
      for (int nt = 0; nt < 4; nt++) {
        int nb = warp_n + nt * 8;
        bf[nt][0] = Bs[(nb + grp) * ASTR + kk + thr];
        bf[nt][1] = Bs[(nb + grp) * ASTR + kk + thr + 4];
      }
#pragma unroll
      for (int mt = 0; mt < 4; mt++)
#pragma unroll
        for (int nt = 0; nt < 4; nt++) {
          float* c = acc[mt][nt];
          asm volatile(
              "mma.sync.aligned.m16n8k8.row.col.f32.tf32.tf32.f32 "
              "{%0,%1,%2,%3}, {%4,%5,%6,%7}, {%8,%9}, {%0,%1,%2,%3};"
              : "+f"(c[0]), "+f"(c[1]), "+f"(c[2]), "+f"(c[3])
              : "r"(af[mt][0]), "r"(af[mt][1]), "r"(af[mt][2]), "r"(af[mt][3]),
                "r"(bf[nt][0]), "r"(bf[nt][1]));
        }
    }
    __syncthreads();
  }

  // Epilogue. c0:(row,col2) c1:(row,col2+1) c2:(row+8,col2) c3:(row+8,col2+1)
#pragma unroll
  for (int mt = 0; mt < 4; mt++) {
#pragma unroll
    for (int nt = 0; nt < 4; nt++) {
      int row = m0 + warp_m + mt * 16 + grp;
      int col = n0 + warp_n + nt * 8 + thr * 2;
      float* c = acc[mt][nt];
      if (MODE == 0) {
        *(float2*)&C[(size_t)row * D_MODEL + col] = make_float2(c[0], c[1]);
        *(float2*)&C[(size_t)(row + 8) * D_MODEL + col] = make_float2(c[2], c[3]);
      } else {
#pragma unroll
        for (int e = 0; e < 4; e++) {
          int r = row + (e >> 1) * 8;
          int n = col + (e & 1);
          int b = r >> 11;
          int ii = r & (L_SEQ - 1);
          int h = n & 15;
          int d = n >> 4;
          C[((((size_t)b * NH + h) * L_SEQ) + ii) * DK + d] = c[e];
        }
      }
    }
  }
}

// ---------------------------------------------------------------------------
// Attention: one block per (b, h, 64-row i-tile). Online softmax over 64-wide
// o-tiles. Q/K stored d-major in smem, V o-major, P i-major.
// ---------------------------------------------------------------------------
__global__ __launch_bounds__(256) void attn_kernel(
    const float* __restrict__ Qh, const float* __restrict__ Kh,
    const float* __restrict__ Vh, const unsigned char* __restrict__ mask,
    float* __restrict__ Mha) {
  extern __shared__ float sm[];
  float* Qs = sm;                        // [64][ST]  Qs[d][i] (scaled)
  float* Ks = sm + 64 * ST;              // [64][ST]  Ks[d][o]
  float* Vs = sm + 2 * 64 * ST;          // [64][ST]  Vs[o][d]
  float* Ps = sm + 3 * 64 * ST;          // [64][ST]  Ps[i][o]
  float* Cs = sm + 4 * 64 * ST;          // [64] per-row rescale factor
  float* Ls = Cs + 64;                   // [64] per-row denom
  unsigned char* Msm = (unsigned char*)(Cs + 128);  // [64][64] mask bytes

  int tid = threadIdx.x;
  int it0 = blockIdx.x * 64;
  int h = blockIdx.y;
  int b = blockIdx.z;
  int bh = b * NH + h;
  const float* Qbase = Qh + (size_t)bh * L_SEQ * DK;
  const float* Kbase = Kh + (size_t)bh * L_SEQ * DK;
  const float* Vbase = Vh + (size_t)bh * L_SEQ * DK;
  const unsigned char* Mbase = mask + (size_t)b * L_SEQ * L_SEQ;

  int ti = tid >> 4, tj = tid & 15;   // 4x4 micro-tile owner
  int sr = tid >> 2, sg = tid & 3;    // softmax: row, quarter

  // Load Q tile transposed + pre-scaled by 1/sqrt(dk)=0.125
  for (int idx = tid; idx < 64 * 16; idx += 256) {
    int i = idx >> 4, dc = (idx & 15) << 2;
    float4 qv = *(const float4*)&Qbase[(size_t)(it0 + i) * DK + dc];
    Qs[(dc + 0) * ST + i] = qv.x * 0.125f;
    Qs[(dc + 1) * ST + i] = qv.y * 0.125f;
    Qs[(dc + 2) * ST + i] = qv.z * 0.125f;
    Qs[(dc + 3) * ST + i] = qv.w * 0.125f;
  }

  float m_run = -CUDART_INF_F;
  float l_run = 0.f;
  float acc[4][4];
#pragma unroll
  for (int r = 0; r < 4; r++)
#pragma unroll
    for (int c = 0; c < 4; c++) acc[r][c] = 0.f;

  for (int ot = 0; ot < L_SEQ / 64; ot++) {
    int o0 = ot * 64;
    // load K (transposed), V (direct), mask tile
    for (int idx = tid; idx < 64 * 16; idx += 256) {
      int o = idx >> 4, dc = (idx & 15) << 2;
      float4 kv = *(const float4*)&Kbase[(size_t)(o0 + o) * DK + dc];
      Ks[(dc + 0) * ST + o] = kv.x;
      Ks[(dc + 1) * ST + o] = kv.y;
      Ks[(dc + 2) * ST + o] = kv.z;
      Ks[(dc + 3) * ST + o] = kv.w;
      float4 vv = *(const float4*)&Vbase[(size_t)(o0 + o) * DK + dc];
      *(float4*)&Vs[o * ST + dc] = vv;
    }
    for (int idx = tid; idx < 64 * 4; idx += 256) {
      int r = idx >> 2, c = idx & 3;
      *(int4*)&Msm[r * 64 + c * 16] =
          *(const int4*)&Mbase[(size_t)(it0 + r) * L_SEQ + o0 + c * 16];
    }
    __syncthreads();

    // S = (Q/8) K^T
    float s[4][4];
#pragma unroll
    for (int r = 0; r < 4; r++)
#pragma unroll
      for (int c = 0; c < 4; c++) s[r][c] = 0.f;
#pragma unroll 16
    for (int d = 0; d < 64; d++) {
      float4 q = *(const float4*)&Qs[d * ST + ti * 4];
      float4 k = *(const float4*)&Ks[d * ST + tj * 4];
      float qa[4] = {q.x, q.y, q.z, q.w};
      float kb[4] = {k.x, k.y, k.z, k.w};
#pragma unroll
      for (int r = 0; r < 4; r++)
#pragma unroll
        for (int c = 0; c < 4; c++) s[r][c] += qa[r] * kb[c];
    }
    // mask + write P tile
#pragma unroll
    for (int r = 0; r < 4; r++) {
      uchar4 mk = *(const uchar4*)&Msm[(ti * 4 + r) * 64 + tj * 4];
      if (mk.x) s[r][0] = -1e10f;
      if (mk.y) s[r][1] = -1e10f;
      if (mk.z) s[r][2] = -1e10f;
      if (mk.w) s[r][3] = -1e10f;
      *(float4*)&Ps[(ti * 4 + r) * ST + tj * 4] =
          make_float4(s[r][0], s[r][1], s[r][2], s[r][3]);
    }
    __syncthreads();

    // online softmax: 4 threads per row, 16 cols each
    {
      float* row = Ps + sr * ST + sg * 16;
      float mx = row[0];
#pragma unroll
      for (int j = 1; j < 16; j++) mx = fmaxf(mx, row[j]);
      mx = fmaxf(mx, __shfl_xor_sync(0xffffffffu, mx, 1));
      mx = fmaxf(mx, __shfl_xor_sync(0xffffffffu, mx, 2));
      float newm = fmaxf(m_run, mx);
      float corr = __expf(m_run - newm);
      float ssum = 0.f;
#pragma unroll
      for (int j = 0; j < 16; j++) {
        float p = __expf(row[j] - newm);
        row[j] = p;
        ssum += p;
      }
      ssum += __shfl_xor_sync(0xffffffffu, ssum, 1);
      ssum += __shfl_xor_sync(0xffffffffu, ssum, 2);
      l_run = l_run * corr + ssum;
      m_run = newm;
      if (sg == 0) Cs[sr] = corr;
    }
    __syncthreads();

    // O = O*corr + P @ V
    {
      float cr[4];
#pragma unroll
      for (int r = 0; r < 4; r++) cr[r] = Cs[ti * 4 + r];
#pragma unroll
      for (int r = 0; r < 4; r++)
#pragma unroll
        for (int c = 0; c < 4; c++) acc[r][c] *= cr[r];
#pragma unroll 16
      for (int o = 0; o < 64; o++) {
        float p0 = Ps[(ti * 4 + 0) * ST + o];
        float p1 = Ps[(ti * 4 + 1) * ST + o];
        float p2 = Ps[(ti * 4 + 2) * ST + o];
        float p3 = Ps[(ti * 4 + 3) * ST + o];
        float4 v = *(const float4*)&Vs[o * ST + tj * 4];
        float vb[4] = {v.x, v.y, v.z, v.w};
#pragma unroll
        for (int c = 0; c < 4; c++) {
          acc[0][c] += p0 * vb[c];
          acc[1][c] += p1 * vb[c];
          acc[2][c] += p2 * vb[c];
          acc[3][c] += p3 * vb[c];
        }
      }
    }
    __syncthreads();
  }

  if (sg == 0) Ls[sr] = l_run;
  __syncthreads();

  float inv[4];
#pragma unroll
  for (int r = 0; r < 4; r++) inv[r] = 1.0f / Ls[ti * 4 + r];
#pragma unroll
  for (int r = 0; r < 4; r++) {
    int i = it0 + ti * 4 + r;
#pragma unroll
    for (int c = 0; c < 4; c++) {
      int d = tj * 4 + c;
      Mha[(size_t)(b * L_SEQ + i) * D_MODEL + d * 16 + h] = acc[r][c] * inv[r];
    }
  }
}

// ---------------------------------------------------------------------------
extern "C" void kernel_launch(void* const* d_in, const int* in_sizes, int n_in,
                              void* d_out, int out_size) {
  const float* q = (const float*)d_in[0];
  const float* k = (const float*)d_in[1];
  const float* v = (const float*)d_in[2];
  const int* mask4 = (const int*)d_in[3];
  const float* Wq = (const float*)d_in[4];
  const float* Wk = (const float*)d_in[5];
  const float* Wv = (const float*)d_in[6];
  const float* Wo = (const float*)d_in[7];
  float* out = (float*)d_out;

  float *Qh, *Kh, *Vh, *Mh;
  unsigned char* Mk;
  cudaGetSymbolAddress((void**)&Qh, g_Qh);
  cudaGetSymbolAddress((void**)&Kh, g_Kh);
  cudaGetSymbolAddress((void**)&Vh, g_Vh);
  cudaGetSymbolAddress((void**)&Mh, g_Mha);
  cudaGetSymbolAddress((void**)&Mk, g_mask);

  int nmask = B_SZ * L_SEQ * L_SEQ;
  mask_cvt_kernel<<<nmask / 4 / 256, 256>>>(mask4, Mk);

  dim3 gg(D_MODEL / 128, M_TOT / 128);  // (8, 32)
  gemm_tf32_kernel<1><<<gg, 256>>>(q, Wq, Qh);
  gemm_tf32_kernel<1><<<gg, 256>>>(k, Wk, Kh);
  gemm_tf32_kernel<1><<<gg, 256>>>(v, Wv, Vh);

  int smem_bytes = (4 * 64 * ST + 128) * 4 + 64 * 64;  // 74240
  cudaFuncSetAttribute(attn_kernel,
                       cudaFuncAttributeMaxDynamicSharedMemorySize, smem_bytes);
  dim3 ag(L_SEQ / 64, NH, B_SZ);
  attn_kernel<<<ag, 256, smem_bytes>>>(Qh, Kh, Vh, Mk, Mh);

  gemm_tf32_kernel<0><<<gg, 256>>>(Mh, Wo, out);
}

// round 4
// speedup vs baseline: 2.9418x; 2.0429x over previous
#include <cuda_runtime.h>
#include <math_constants.h>

#define B_SZ 2
#define L_SEQ 2048
#define D_MODEL 1024
#define NH 16
#define DK 64
#define M_TOT (B_SZ * L_SEQ)
#define NEG (-1e10f)

// Scratch (device globals — no cudaMalloc allowed)
__device__ float g_Qh[B_SZ * NH * L_SEQ * DK];   // [b][h][i][d]
__device__ float g_Kh[B_SZ * NH * L_SEQ * DK];   // [b][h][o][d]
__device__ float g_Vt[B_SZ * NH * DK * L_SEQ];   // [b][h][d][o]  (transposed!)
__device__ float g_Mha[M_TOT * D_MODEL];         // [b*L+i][d*16+h]
__device__ unsigned g_mbits[B_SZ * L_SEQ * L_SEQ / 32];  // bit-packed mask

__device__ __forceinline__ unsigned f2tf32(float v) {
  unsigned r;
  asm("cvt.rna.tf32.f32 %0, %1;" : "=r"(r) : "f"(v));
  return r;
}

// ---------------------------------------------------------------------------
// Mask: 4-byte bool elements -> bit-packed (bit set == masked)
// One thread packs 32 elements into one word.
// ---------------------------------------------------------------------------
__global__ __launch_bounds__(256) void mask_bits_kernel(
    const int* __restrict__ m4, unsigned* __restrict__ out) {
  int w = blockIdx.x * 256 + threadIdx.x;
  const int4* p = (const int4*)m4 + (size_t)w * 8;
  unsigned bits = 0;
#pragma unroll
  for (int j = 0; j < 8; j++) {
    int4 v = p[j];
    bits |= (unsigned)(v.x != 0) << (4 * j + 0);
    bits |= (unsigned)(v.y != 0) << (4 * j + 1);
    bits |= (unsigned)(v.z != 0) << (4 * j + 2);
    bits |= (unsigned)(v.w != 0) << (4 * j + 3);
  }
  out[w] = bits;
}

// ---------------------------------------------------------------------------
// TF32 tensor-core GEMM: C[m,n] = sum_k A[m,k] * W[n,k]
// MODE 0: C[m*1024+n]
// MODE 1: head-scatter C[(((b*16+h)*2048)+i)*64+d]        (Q, K)
// MODE 2: head-scatter transposed C[(((b*16+h)*64)+d)*2048+i]  (V)
// ---------------------------------------------------------------------------
#define ASTR 36
template <int MODE>
__global__ __launch_bounds__(256) void gemm_tf32_kernel(
    const float* __restrict__ A, const float* __restrict__ W,
    float* __restrict__ C) {
  const int K = D_MODEL;
  __shared__ unsigned As[128 * ASTR];
  __shared__ unsigned Bs[128 * ASTR];

  int tid = threadIdx.x;
  int m0 = blockIdx.y * 128;
  int n0 = blockIdx.x * 128;
  int wid = tid >> 5;
  int lane = tid & 31;
  int warp_m = (wid & 1) * 64;
  int warp_n = (wid >> 1) * 32;
  int grp = lane >> 2;
  int thr = lane & 3;

  float acc[4][4][4];
#pragma unroll
  for (int i = 0; i < 4; i++)
#pragma unroll
    for (int j = 0; j < 4; j++)
#pragma unroll
      for (int r = 0; r < 4; r++) acc[i][j][r] = 0.f;

  int lr = tid >> 3;
  int lc = (tid & 7) * 4;

  for (int k0 = 0; k0 < K; k0 += 32) {
#pragma unroll
    for (int s = 0; s < 4; s++) {
      int r = lr + s * 32;
      float4 a = *(const float4*)&A[(size_t)(m0 + r) * K + k0 + lc];
      As[r * ASTR + lc + 0] = f2tf32(a.x);
      As[r * ASTR + lc + 1] = f2tf32(a.y);
      As[r * ASTR + lc + 2] = f2tf32(a.z);
      As[r * ASTR + lc + 3] = f2tf32(a.w);
      float4 w = *(const float4*)&W[(size_t)(n0 + r) * K + k0 + lc];
      Bs[r * ASTR + lc + 0] = f2tf32(w.x);
      Bs[r * ASTR + lc + 1] = f2tf32(w.y);
      Bs[r * ASTR + lc + 2] = f2tf32(w.z);
      Bs[r * ASTR + lc + 3] = f2tf32(w.w);
    }
    __syncthreads();

#pragma unroll
    for (int kk = 0; kk < 32; kk += 8) {
      unsigned af[4][4], bf[4][2];
#pragma unroll
      for (int mt = 0; mt < 4; mt++) {
        int rb = warp_m + mt * 16;
        af[mt][0] = As[(rb + grp) * ASTR + kk + thr];
        af[mt][1] = As[(rb + grp + 8) * ASTR + kk + thr];
        af[mt][2] = As[(rb + grp) * ASTR + kk + thr + 4];
        af[mt][3] = As[(rb + grp + 8) * ASTR + kk + thr + 4];
      }
#pragma unroll
      for (int nt = 0; nt < 4; nt++) {
        int nb = warp_n + nt * 8;
        bf[nt][0] = Bs[(nb + grp) * ASTR + kk + thr];
        bf[nt][1] = Bs[(nb + grp) * ASTR + kk + thr + 4];
      }
#pragma unroll
      for (int mt = 0; mt < 4; mt++)
#pragma unroll
        for (int nt = 0; nt < 4; nt++) {
          float* c = acc[mt][nt];
          asm volatile(
              "mma.sync.aligned.m16n8k8.row.col.f32.tf32.tf32.f32 "
              "{%0,%1,%2,%3}, {%4,%5,%6,%7}, {%8,%9}, {%0,%1,%2,%3};"
              : "+f"(c[0]), "+f"(c[1]), "+f"(c[2]), "+f"(c[3])
              : "r"(af[mt][0]), "r"(af[mt][1]), "r"(af[mt][2]), "r"(af[mt][3]),
                "r"(bf[nt][0]), "r"(bf[nt][1]));
        }
    }
    __syncthreads();
  }

#pragma unroll
  for (int mt = 0; mt < 4; mt++) {
#pragma unroll
    for (int nt = 0; nt < 4; nt++) {
      int row = m0 + warp_m + mt * 16 + grp;
      int col = n0 + warp_n + nt * 8 + thr * 2;
      float* c = acc[mt][nt];
      if (MODE == 0) {
        *(float2*)&C[(size_t)row * D_MODEL + col] = make_float2(c[0], c[1]);
        *(float2*)&C[(size_t)(row + 8) * D_MODEL + col] = make_float2(c[2], c[3]);
      } else {
#pragma unroll
        for (int e = 0; e < 4; e++) {
          int r = row + (e >> 1) * 8;
          int n = col + (e & 1);
          int b = r >> 11;
          int ii = r & (L_SEQ - 1);
          int h = n & 15;
          int d = n >> 4;
          if (MODE == 1)
            C[((((size_t)b * NH + h) * L_SEQ) + ii) * DK + d] = c[e];
          else
            C[((((size_t)b * NH + h) * DK) + d) * L_SEQ + ii] = c[e];
        }
      }
    }
  }
}

// ---------------------------------------------------------------------------
// TF32 tensor-core flash attention.
// CTA: (b, h, 128 i-rows). 8 warps x 16 rows. o-tiles of 64.
// Smem: Ks[64][68] tf32, Vs[64][68] tf32 (V^T rows=d), Ps[128][68] (Q staging,
// then P). Register online softmax per quad.
// ---------------------------------------------------------------------------
#define PSTR 68
__global__ __launch_bounds__(256) void attn_mma_kernel(
    const float* __restrict__ Qh, const float* __restrict__ Kh,
    const float* __restrict__ Vt, const unsigned* __restrict__ mbits,
    float* __restrict__ Mha) {
  extern __shared__ unsigned smu[];
  unsigned* Ks = smu;                 // [64][PSTR]
  unsigned* Vs = smu + 64 * PSTR;     // [64][PSTR]
  unsigned* Ps = smu + 128 * PSTR;    // [128][PSTR]

  int tid = threadIdx.x;
  int w = tid >> 5;
  int lane = tid & 31;
  int grp = lane >> 2;
  int thr = lane & 3;
  int i0 = blockIdx.x * 128;
  int h = blockIdx.y;
  int b = blockIdx.z;
  int bh = b * NH + h;
  const float* Qb = Qh + (size_t)bh * L_SEQ * DK;
  const float* Kb = Kh + (size_t)bh * L_SEQ * DK;
  const float* Vb = Vt + (size_t)bh * DK * L_SEQ;

  // Stage Q (scaled, tf32) into Ps, then pull persistent A-fragments
  for (int idx = tid; idx < 128 * 16; idx += 256) {
    int i = idx >> 4, dc = (idx & 15) << 2;
    float4 qv = *(const float4*)&Qb[(size_t)(i0 + i) * DK + dc];
    unsigned* dst = &Ps[i * PSTR + dc];
    dst[0] = f2tf32(qv.x * 0.125f);
    dst[1] = f2tf32(qv.y * 0.125f);
    dst[2] = f2tf32(qv.z * 0.125f);
    dst[3] = f2tf32(qv.w * 0.125f);
  }
  __syncthreads();

  int rbase = w * 16;
  unsigned Qf[8][4];
#pragma unroll
  for (int kg = 0; kg < 8; kg++) {
    Qf[kg][0] = Ps[(rbase + grp) * PSTR + kg * 8 + thr];
    Qf[kg][1] = Ps[(rbase + grp + 8) * PSTR + kg * 8 + thr];
    Qf[kg][2] = Ps[(rbase + grp) * PSTR + kg * 8 + thr + 4];
    Qf[kg][3] = Ps[(rbase + grp + 8) * PSTR + kg * 8 + thr + 4];
  }
  __syncthreads();

  int rA = i0 + rbase + grp;
  int rB = rA + 8;
  const unsigned long long* mbA =
      (const unsigned long long*)mbits + (size_t)(b * L_SEQ + rA) * (L_SEQ / 64);
  const unsigned long long* mbB =
      (const unsigned long long*)mbits + (size_t)(b * L_SEQ + rB) * (L_SEQ / 64);

  float mA = -CUDART_INF_F, mB = -CUDART_INF_F;
  float lA = 0.f, lB = 0.f;
  float oa[8][4];
#pragma unroll
  for (int nt = 0; nt < 8; nt++)
#pragma unroll
    for (int e = 0; e < 4; e++) oa[nt][e] = 0.f;

  for (int ot = 0; ot < L_SEQ / 64; ot++) {
    int o0 = ot * 64;
    // Load K tile [o][d] and V^T tile [d][o] (both conflict-free row stores)
    for (int idx = tid; idx < 64 * 16; idx += 256) {
      int r = idx >> 4, c = (idx & 15) << 2;
      float4 kv = *(const float4*)&Kb[(size_t)(o0 + r) * DK + c];
      unsigned* kd = &Ks[r * PSTR + c];
      kd[0] = f2tf32(kv.x);
      kd[1] = f2tf32(kv.y);
      kd[2] = f2tf32(kv.z);
      kd[3] = f2tf32(kv.w);
      float4 vv = *(const float4*)&Vb[(size_t)r * L_SEQ + o0 + c];
      unsigned* vd = &Vs[r * PSTR + c];
      vd[0] = f2tf32(vv.x);
      vd[1] = f2tf32(vv.y);
      vd[2] = f2tf32(vv.z);
      vd[3] = f2tf32(vv.w);
    }
    __syncthreads();

    unsigned long long mWa = mbA[ot];
    unsigned long long mWb = mbB[ot];

    // S = Q K^T  (16 x 64 per warp)
    float sa[8][4];
#pragma unroll
    for (int nt = 0; nt < 8; nt++) {
      sa[nt][0] = sa[nt][1] = sa[nt][2] = sa[nt][3] = 0.f;
#pragma unroll
      for (int kg = 0; kg < 8; kg++) {
        unsigned b0 = Ks[(nt * 8 + grp) * PSTR + kg * 8 + thr];
        unsigned b1 = Ks[(nt * 8 + grp) * PSTR + kg * 8 + thr + 4];
        float* c = sa[nt];
        asm volatile(
            "mma.sync.aligned.m16n8k8.row.col.f32.tf32.tf32.f32 "
            "{%0,%1,%2,%3}, {%4,%5,%6,%7}, {%8,%9}, {%0,%1,%2,%3};"
            : "+f"(c[0]), "+f"(c[1]), "+f"(c[2]), "+f"(c[3])
            : "r"(Qf[kg][0]), "r"(Qf[kg][1]), "r"(Qf[kg][2]), "r"(Qf[kg][3]),
              "r"(b0), "r"(b1));
      }
    }

    // Mask + row max (register)
    float mxA = -CUDART_INF_F, mxB = -CUDART_INF_F;
#pragma unroll
    for (int nt = 0; nt < 8; nt++) {
      int c0 = nt * 8 + 2 * thr;
      if ((mWa >> c0) & 1ull) sa[nt][0] = NEG;
      if ((mWa >> (c0 + 1)) & 1ull) sa[nt][1] = NEG;
      if ((mWb >> c0) & 1ull) sa[nt][2] = NEG;
      if ((mWb >> (c0 + 1)) & 1ull) sa[nt][3] = NEG;
      mxA = fmaxf(mxA, fmaxf(sa[nt][0], sa[nt][1]));
      mxB = fmaxf(mxB, fmaxf(sa[nt][2], sa[nt][3]));
    }
    mxA = fmaxf(mxA, __shfl_xor_sync(0xffffffffu, mxA, 1));
    mxA = fmaxf(mxA, __shfl_xor_sync(0xffffffffu, mxA, 2));
    mxB = fmaxf(mxB, __shfl_xor_sync(0xffffffffu, mxB, 1));
    mxB = fmaxf(mxB, __shfl_xor_sync(0xffffffffu, mxB, 2));

    float nmA = fmaxf(mA, mxA), nmB = fmaxf(mB, mxB);
    float cA = __expf(mA - nmA), cB = __expf(mB - nmB);
    float sumA = 0.f, sumB = 0.f;
#pragma unroll
    for (int nt = 0; nt < 8; nt++) {
      float p0 = __expf(sa[nt][0] - nmA);
      float p1 = __expf(sa[nt][1] - nmA);
      float p2 = __expf(sa[nt][2] - nmB);
      float p3 = __expf(sa[nt][3] - nmB);
      sumA += p0 + p1;
      sumB += p2 + p3;
      uint2 u01 = make_uint2(f2tf32(p0), f2tf32(p1));
      uint2 u23 = make_uint2(f2tf32(p2), f2tf32(p3));
      *(uint2*)&Ps[(rbase + grp) * PSTR + nt * 8 + 2 * thr] = u01;
      *(uint2*)&Ps[(rbase + grp + 8) * PSTR + nt * 8 + 2 * thr] = u23;
    }
    sumA += __shfl_xor_sync(0xffffffffu, sumA, 1);
    sumA += __shfl_xor_sync(0xffffffffu, sumA, 2);
    sumB += __shfl_xor_sync(0xffffffffu, sumB, 1);
    sumB += __shfl_xor_sync(0xffffffffu, sumB, 2);
    lA = lA * cA + sumA;
    lB = lB * cB + sumB;
    mA = nmA;
    mB = nmB;

    // Rescale O accumulators
#pragma unroll
    for (int nt = 0; nt < 8; nt++) {
      oa[nt][0] *= cA;
      oa[nt][1] *= cA;
      oa[nt][2] *= cB;
      oa[nt][3] *= cB;
    }
    __syncwarp();

    // O += P V   (A-frags from Ps, B-frags from Vs = V^T)
    unsigned pf[8][4];
#pragma unroll
    for (int kg = 0; kg < 8; kg++) {
      pf[kg][0] = Ps[(rbase + grp) * PSTR + kg * 8 + thr];
      pf[kg][1] = Ps[(rbase + grp + 8) * PSTR + kg * 8 + thr];
      pf[kg][2] = Ps[(rbase + grp) * PSTR + kg * 8 + thr + 4];
      pf[kg][3] = Ps[(rbase + grp + 8) * PSTR + kg * 8 + thr + 4];
    }
#pragma unroll
    for (int nt = 0; nt < 8; nt++) {
#pragma unroll
      for (int kg = 0; kg < 8; kg++) {
        unsigned b0 = Vs[(nt * 8 + grp) * PSTR + kg * 8 + thr];
        unsigned b1 = Vs[(nt * 8 + grp) * PSTR + kg * 8 + thr + 4];
        float* c = oa[nt];
        asm volatile(
            "mma.sync.aligned.m16n8k8.row.col.f32.tf32.tf32.f32 "
            "{%0,%1,%2,%3}, {%4,%5,%6,%7}, {%8,%9}, {%0,%1,%2,%3};"
            : "+f"(c[0]), "+f"(c[1]), "+f"(c[2]), "+f"(c[3])
            : "r"(pf[kg][0]), "r"(pf[kg][1]), "r"(pf[kg][2]), "r"(pf[kg][3]),
              "r"(b0), "r"(b1));
      }
    }
    __syncthreads();
  }

  float iA = 1.f / lA, iB = 1.f / lB;
  float* outA = &Mha[(size_t)(b * L_SEQ + rA) * D_MODEL + h];
  float* outB = &Mha[(size_t)(b * L_SEQ + rB) * D_MODEL + h];
#pragma unroll
  for (int nt = 0; nt < 8; nt++) {
    int d0 = nt * 8 + 2 * thr;
    outA[(d0 + 0) * 16] = oa[nt][0] * iA;
    outA[(d0 + 1) * 16] = oa[nt][1] * iA;
    outB[(d0 + 0) * 16] = oa[nt][2] * iB;
    outB[(d0 + 1) * 16] = oa[nt][3] * iB;
  }
}

// ---------------------------------------------------------------------------
extern "C" void kernel_launch(void* const* d_in, const int* in_sizes, int n_in,
                              void* d_out, int out_size) {
  const float* q = (const float*)d_in[0];
  const float* k = (const float*)d_in[1];
  const float* v = (const float*)d_in[2];
  const int* mask4 = (const int*)d_in[3];
  const float* Wq = (const float*)d_in[4];
  const float* Wk = (const float*)d_in[5];
  const float* Wv = (const float*)d_in[6];
  const float* Wo = (const float*)d_in[7];
  float* out = (float*)d_out;

  float *Qh, *Kh, *Vt, *Mh;
  unsigned* Mb;
  cudaGetSymbolAddress((void**)&Qh, g_Qh);
  cudaGetSymbolAddress((void**)&Kh, g_Kh);
  cudaGetSymbolAddress((void**)&Vt, g_Vt);
  cudaGetSymbolAddress((void**)&Mh, g_Mha);
  cudaGetSymbolAddress((void**)&Mb, g_mbits);

  int nwords = B_SZ * L_SEQ * L_SEQ / 32;  // 262144
  mask_bits_kernel<<<nwords / 256, 256>>>(mask4, Mb);

  dim3 gg(D_MODEL / 128, M_TOT / 128);  // (8, 32)
  gemm_tf32_kernel<1><<<gg, 256>>>(q, Wq, Qh);
  gemm_tf32_kernel<1><<<gg, 256>>>(k, Wk, Kh);
  gemm_tf32_kernel<2><<<gg, 256>>>(v, Wv, Vt);

  int smem_bytes = (128 * PSTR + 128 * PSTR) * 4;  // 69632
  cudaFuncSetAttribute(attn_mma_kernel,
                       cudaFuncAttributeMaxDynamicSharedMemorySize, smem_bytes);
  dim3 ag(L_SEQ / 128, NH, B_SZ);  // (16, 16, 2)
  attn_mma_kernel<<<ag, 256, smem_bytes>>>(Qh, Kh, Vt, Mb, Mh);

  gemm_tf32_kernel<0><<<gg, 256>>>(Mh, Wo, out);
}